// round 1
// baseline (speedup 1.0000x reference)
#include <cuda_runtime.h>
#include <cstdint>

#define N_NODES 100000
#define N_EDGES 1000000
#define NHID    128
#define NB_EDGE 2048

// ---------------- scratch (device globals; no allocation allowed) ----------
__device__ float g_A[(size_t)N_NODES * NHID];   // feature @ W1[:128]
__device__ float g_B[(size_t)N_NODES * NHID];   // feature @ W1[128:]
__device__ int   g_row[N_EDGES];
__device__ int   g_col[N_EDGES];
__device__ int   g_lab[N_NODES];
__device__ int   g_is64;
__device__ float g_part[NB_EDGE];

// ---------------- f32x2 packed-FMA helpers (Blackwell FFMA2 path) ----------
__device__ __forceinline__ unsigned long long dup2(float x) {
    unsigned long long r;
    asm("mov.b64 %0, {%1, %1};" : "=l"(r) : "f"(x));
    return r;
}
__device__ __forceinline__ void fma2(unsigned long long& d,
                                     unsigned long long a,
                                     unsigned long long b) {
    asm("fma.rn.f32x2 %0, %1, %2, %0;" : "+l"(d) : "l"(a), "l"(b));
}

// ---------------- 1) dtype sniff: int64 vs int32 index buffers -------------
__global__ void k_detect(const void* row) {
    if (threadIdx.x == 0 && blockIdx.x == 0) {
        const unsigned long long* p = (const unsigned long long*)row;
        int is64 = 1;
        for (int i = 0; i < 64; i++)
            if (p[i] >= (1ULL << 32)) is64 = 0;
        g_is64 = is64;
    }
}

// ---------------- 2) normalize indices/labels to int32 ---------------------
__global__ void k_convert(const void* row, const void* col, const void* lab) {
    const int is64 = g_is64;
    const int tid = blockIdx.x * blockDim.x + threadIdx.x;
    const int stride = gridDim.x * blockDim.x;
    if (is64) {
        const long long* r = (const long long*)row;
        const long long* c = (const long long*)col;
        const long long* l = (const long long*)lab;
        for (int e = tid; e < N_EDGES; e += stride) {
            g_row[e] = (int)r[e];
            g_col[e] = (int)c[e];
        }
        for (int n = tid; n < N_NODES; n += stride) g_lab[n] = (int)l[n];
    } else {
        const int* r = (const int*)row;
        const int* c = (const int*)col;
        const int* l = (const int*)lab;
        for (int e = tid; e < N_EDGES; e += stride) {
            g_row[e] = r[e];
            g_col[e] = c[e];
        }
        for (int n = tid; n < N_NODES; n += stride) g_lab[n] = l[n];
    }
}

// ---------------- 3) node GEMM: A = F@W1_top, B = F@W1_bot ------------------
// grid = (ceil(N/64), 2), block = 256.  Tile: 64 rows x 128 cols, K-tile 32.
// Per thread: 4 rows x 8 cols, accumulated as 4x4 f32x2 pairs via FFMA2.
__global__ void __launch_bounds__(256) k_gemm(const float* __restrict__ feat,
                                              const float* __restrict__ W1) {
    __shared__ float As[64 * 32];
    __shared__ float Ws[32 * 128];

    const int half = blockIdx.y;
    const int row0 = blockIdx.x * 64;
    const float* Wbase = W1 + (size_t)half * 128 * 128;
    float* out = half ? g_B : g_A;

    const int t  = threadIdx.x;
    const int rg = t >> 4;          // 0..15 -> rows rg*4 .. rg*4+3
    const int cg = t & 15;          // 0..15 -> cols cg*8 .. cg*8+7

    // As loader mapping: thread loads 8 floats of one row
    const int lr = t >> 2;          // 0..63
    const int lc = (t & 3) * 8;     // 0,8,16,24
    // Ws loader mapping: thread loads 16 floats of one row
    const int wr = t >> 3;          // 0..31
    const int wc = (t & 7) * 16;    // 0..112

    unsigned long long acc[4][4];
#pragma unroll
    for (int r = 0; r < 4; r++)
#pragma unroll
        for (int p = 0; p < 4; p++) acc[r][p] = 0ULL;

    for (int k0 = 0; k0 < 128; k0 += 32) {
        // load feature tile (guarded)
        {
            float4 v0 = make_float4(0.f, 0.f, 0.f, 0.f), v1 = v0;
            const int grow = row0 + lr;
            if (grow < N_NODES) {
                const float4* p =
                    (const float4*)(feat + (size_t)grow * NHID + k0 + lc);
                v0 = p[0];
                v1 = p[1];
            }
            *(float4*)&As[lr * 32 + lc]     = v0;
            *(float4*)&As[lr * 32 + lc + 4] = v1;
        }
        // load weight tile
        {
            const float4* p =
                (const float4*)(Wbase + (size_t)(k0 + wr) * 128 + wc);
            float4 w0 = p[0], w1 = p[1], w2 = p[2], w3 = p[3];
            *(float4*)&Ws[wr * 128 + wc]      = w0;
            *(float4*)&Ws[wr * 128 + wc + 4]  = w1;
            *(float4*)&Ws[wr * 128 + wc + 8]  = w2;
            *(float4*)&Ws[wr * 128 + wc + 12] = w3;
        }
        __syncthreads();

#pragma unroll
        for (int k = 0; k < 32; k += 4) {
            float4 av[4];
#pragma unroll
            for (int r = 0; r < 4; r++)
                av[r] = *(const float4*)&As[(rg * 4 + r) * 32 + k];
#pragma unroll
            for (int kk = 0; kk < 4; kk++) {
                ulonglong2 wv0 =
                    *(const ulonglong2*)(Ws + (k + kk) * 128 + cg * 8);
                ulonglong2 wv1 =
                    *(const ulonglong2*)(Ws + (k + kk) * 128 + cg * 8 + 4);
#pragma unroll
                for (int r = 0; r < 4; r++) {
                    const float a = (&av[r].x)[kk];
                    const unsigned long long ad = dup2(a);
                    fma2(acc[r][0], ad, wv0.x);
                    fma2(acc[r][1], ad, wv0.y);
                    fma2(acc[r][2], ad, wv1.x);
                    fma2(acc[r][3], ad, wv1.y);
                }
            }
        }
        __syncthreads();
    }

#pragma unroll
    for (int r = 0; r < 4; r++) {
        const int grow = row0 + rg * 4 + r;
        if (grow < N_NODES) {
            float* op = out + (size_t)grow * NHID + cg * 8;
            ulonglong2 o0; o0.x = acc[r][0]; o0.y = acc[r][1];
            ulonglong2 o1; o1.x = acc[r][2]; o1.y = acc[r][3];
            *(ulonglong2*)op       = o0;
            *(ulonglong2*)(op + 4) = o1;
        }
    }
}

// ---------------- 4) edge phase: gather + bias + PReLU + 2-dot + CE --------
// One warp per edge (grid-stride).  Lane l owns h[4l..4l+3].
__global__ void __launch_bounds__(256) k_edge(const float* __restrict__ b1,
                                              const float* __restrict__ alpha,
                                              const float* __restrict__ W2,
                                              const float* __restrict__ b2) {
    __shared__ float s_part[8];
    const int t    = threadIdx.x;
    const int warp = t >> 5;
    const int lane = t & 31;

    // per-lane constants, hoisted out of the edge loop
    const float4 vb1 = *(const float4*)(b1 + lane * 4);
    const float4 val = *(const float4*)(alpha + lane * 4);
    const float4 w20 = *(const float4*)(W2 + lane * 8);      // (W2[i][0],W2[i][1]) pairs
    const float4 w21 = *(const float4*)(W2 + lane * 8 + 4);
    const float  b20 = b2[0];
    const float  b21 = b2[1];

    float wsum = 0.f;
    const int estep = gridDim.x * 8;
    for (int e = blockIdx.x * 8 + warp; e < N_EDGES; e += estep) {
        const int r = g_row[e];
        const int c = g_col[e];
        const float4 a  = *(const float4*)(g_A + (size_t)r * NHID + lane * 4);
        const float4 bv = *(const float4*)(g_B + (size_t)c * NHID + lane * 4);

        float h0 = a.x + bv.x + vb1.x;
        float h1 = a.y + bv.y + vb1.y;
        float h2 = a.z + bv.z + vb1.z;
        float h3 = a.w + bv.w + vb1.w;
        h0 = h0 >= 0.f ? h0 : h0 * val.x;
        h1 = h1 >= 0.f ? h1 : h1 * val.y;
        h2 = h2 >= 0.f ? h2 : h2 * val.z;
        h3 = h3 >= 0.f ? h3 : h3 * val.w;

        float s0 = h0 * w20.x + h1 * w20.z + h2 * w21.x + h3 * w21.z;
        float s1 = h0 * w20.y + h1 * w20.w + h2 * w21.y + h3 * w21.w;
#pragma unroll
        for (int o = 16; o > 0; o >>= 1) {
            s0 += __shfl_xor_sync(0xffffffffu, s0, o);
            s1 += __shfl_xor_sync(0xffffffffu, s1, o);
        }
        if (lane == 0) {
            const float l0 = s0 + b20;
            const float l1 = s1 + b21;
            const int   y  = (g_lab[r] == g_lab[c]) ? 1 : 0;
            const float m  = fmaxf(l0, l1);
            const float lse = m + logf(expf(l0 - m) + expf(l1 - m));
            wsum += lse - (y ? l1 : l0);
        }
    }

    if (lane == 0) s_part[warp] = wsum;
    __syncthreads();
    if (t == 0) {
        float s = 0.f;
#pragma unroll
        for (int w = 0; w < 8; w++) s += s_part[w];
        g_part[blockIdx.x] = s;
    }
}

// ---------------- 5) final reduction -> mean loss ---------------------------
__global__ void k_final(float* out, int out_size) {
    __shared__ double sm[256];
    double s = 0.0;
    for (int i = threadIdx.x; i < NB_EDGE; i += 256) s += (double)g_part[i];
    sm[threadIdx.x] = s;
    __syncthreads();
    for (int o = 128; o > 0; o >>= 1) {
        if (threadIdx.x < o) sm[threadIdx.x] += sm[threadIdx.x + o];
        __syncthreads();
    }
    if (threadIdx.x == 0) out[0] = (float)(sm[0] / (double)N_EDGES);
    // defensively zero any extra output elements
    for (int i = 1 + (int)threadIdx.x; i < out_size; i += 256) out[i] = 0.f;
}

// ---------------- launch ----------------------------------------------------
extern "C" void kernel_launch(void* const* d_in, const int* in_sizes, int n_in,
                              void* d_out, int out_size) {
    const float* feature = (const float*)d_in[0];
    const float* W1      = (const float*)d_in[1];
    const float* b1      = (const float*)d_in[2];
    const float* alpha   = (const float*)d_in[3];
    const float* W2      = (const float*)d_in[4];
    const float* b2      = (const float*)d_in[5];
    const void*  row     = d_in[6];
    const void*  col     = d_in[7];
    const void*  lab     = d_in[8];

    k_detect<<<1, 32>>>(row);
    k_convert<<<512, 256>>>(row, col, lab);

    dim3 ggrid((N_NODES + 63) / 64, 2);
    k_gemm<<<ggrid, 256>>>(feature, W1);

    k_edge<<<NB_EDGE, 256>>>(b1, alpha, W2, b2);
    k_final<<<1, 256>>>((float*)d_out, out_size);
}

// round 3
// speedup vs baseline: 2.2511x; 2.2511x over previous
#include <cuda_runtime.h>
#include <cuda_bf16.h>
#include <cstdint>

#define N_NODES 100000
#define N_EDGES 1000000
#define NHID    128
#define NB_EDGE 2048
#define SA_STRIDE 136   // 128 + 8 pad: row stride 272 B -> ldmatrix conflict-free

// ---------------- scratch (device globals; no allocation allowed) ----------
__device__ __nv_bfloat16 g_A[(size_t)N_NODES * NHID];  // feature @ W1[:128]  (bf16)
__device__ __nv_bfloat16 g_B[(size_t)N_NODES * NHID];  // feature @ W1[128:]  (bf16)
__device__ int   g_row[N_EDGES];
__device__ int   g_col[N_EDGES];
__device__ int   g_lab[N_NODES];
__device__ int   g_is64;
__device__ float g_part[NB_EDGE];

// ---------------- 1) dtype sniff: int64 vs int32 index buffers -------------
__global__ void k_detect(const void* row) {
    if (threadIdx.x == 0 && blockIdx.x == 0) {
        const unsigned long long* p = (const unsigned long long*)row;
        int is64 = 1;
        for (int i = 0; i < 64; i++)
            if (p[i] >= (1ULL << 32)) is64 = 0;
        g_is64 = is64;
    }
}

// ---------------- 2) normalize indices/labels to int32 ---------------------
__global__ void k_convert(const void* row, const void* col, const void* lab) {
    const int is64 = g_is64;
    const int tid = blockIdx.x * blockDim.x + threadIdx.x;
    const int stride = gridDim.x * blockDim.x;
    if (is64) {
        const long long* r = (const long long*)row;
        const long long* c = (const long long*)col;
        const long long* l = (const long long*)lab;
        for (int e = tid; e < N_EDGES; e += stride) {
            g_row[e] = (int)r[e];
            g_col[e] = (int)c[e];
        }
        for (int n = tid; n < N_NODES; n += stride) g_lab[n] = (int)l[n];
    } else {
        const int* r = (const int*)row;
        const int* c = (const int*)col;
        const int* l = (const int*)lab;
        for (int e = tid; e < N_EDGES; e += stride) {
            g_row[e] = r[e];
            g_col[e] = c[e];
        }
        for (int n = tid; n < N_NODES; n += stride) g_lab[n] = l[n];
    }
}

// ---------------- 3) node GEMM via bf16 HMMA --------------------------------
// grid = (ceil(N/128), 2), block = 256 (8 warps).
// Block tile: 128 rows x 128 cols, K = 128 (whole reduction, no k-split).
// Warp w computes rows [w*16, w*16+16) x all 128 cols with m16n8k16 MMA.
extern __shared__ __nv_bfloat16 smem_dyn[];

__global__ void __launch_bounds__(256) k_gemm(const float* __restrict__ feat,
                                              const float* __restrict__ W1) {
    __nv_bfloat16* sA = smem_dyn;                       // [128][SA_STRIDE]
    __nv_bfloat16* sW = smem_dyn + 128 * SA_STRIDE;     // [128][SA_STRIDE] (k-major)

    const int half = blockIdx.y;
    const int row0 = blockIdx.x * 128;
    const float* Wb = W1 + (size_t)half * 128 * 128;
    __nv_bfloat16* out = half ? g_B : g_A;
    const int t = threadIdx.x;

    // Stage + convert fp32 -> bf16 into smem (4096 float4 each for A and W)
    for (int i = t; i < 4096; i += 256) {
        const int r = i >> 5;
        const int c4 = (i & 31) * 4;
        float4 v = make_float4(0.f, 0.f, 0.f, 0.f);
        if (row0 + r < N_NODES)
            v = *(const float4*)(feat + (size_t)(row0 + r) * NHID + c4);
        *(__nv_bfloat162*)&sA[r * SA_STRIDE + c4]     = __floats2bfloat162_rn(v.x, v.y);
        *(__nv_bfloat162*)&sA[r * SA_STRIDE + c4 + 2] = __floats2bfloat162_rn(v.z, v.w);

        const float4 w = *(const float4*)(Wb + (size_t)r * NHID + c4);
        *(__nv_bfloat162*)&sW[r * SA_STRIDE + c4]     = __floats2bfloat162_rn(w.x, w.y);
        *(__nv_bfloat162*)&sW[r * SA_STRIDE + c4 + 2] = __floats2bfloat162_rn(w.z, w.w);
    }
    __syncthreads();

    const int warp = t >> 5;
    const int lane = t & 31;
    const int m0 = warp * 16;

    // Load all A fragments for this warp's 16 rows (8 k-tiles of 16)
    uint32_t a[8][4];
    {
        const int grp = lane >> 3;                       // 0..3
        const int arow = m0 + (grp & 1) * 8 + (lane & 7);
        const int acol = (grp >> 1) * 8;
#pragma unroll
        for (int kt = 0; kt < 8; kt++) {
            uint32_t addr = (uint32_t)__cvta_generic_to_shared(
                &sA[arow * SA_STRIDE + kt * 16 + acol]);
            asm volatile(
                "ldmatrix.sync.aligned.m8n8.x4.shared.b16 {%0,%1,%2,%3}, [%4];"
                : "=r"(a[kt][0]), "=r"(a[kt][1]), "=r"(a[kt][2]), "=r"(a[kt][3])
                : "r"(addr));
        }
    }

    float acc[16][4];
#pragma unroll
    for (int nt = 0; nt < 16; nt++)
#pragma unroll
        for (int j = 0; j < 4; j++) acc[nt][j] = 0.f;

    const int krow_lane = lane & 15;
#pragma unroll
    for (int nt = 0; nt < 16; nt++) {
        const int n0 = nt * 8;
#pragma unroll
        for (int kt = 0; kt < 8; kt++) {
            uint32_t b0, b1;
            uint32_t baddr = (uint32_t)__cvta_generic_to_shared(
                &sW[(kt * 16 + krow_lane) * SA_STRIDE + n0]);
            asm volatile(
                "ldmatrix.sync.aligned.m8n8.x2.trans.shared.b16 {%0,%1}, [%2];"
                : "=r"(b0), "=r"(b1) : "r"(baddr));
            asm volatile(
                "mma.sync.aligned.m16n8k16.row.col.f32.bf16.bf16.f32 "
                "{%0,%1,%2,%3}, {%4,%5,%6,%7}, {%8,%9}, {%0,%1,%2,%3};"
                : "+f"(acc[nt][0]), "+f"(acc[nt][1]), "+f"(acc[nt][2]), "+f"(acc[nt][3])
                : "r"(a[kt][0]), "r"(a[kt][1]), "r"(a[kt][2]), "r"(a[kt][3]),
                  "r"(b0), "r"(b1));
        }
    }

    // Epilogue: fp32 accum -> bf16, direct global store
    const int tq = lane >> 2;          // row within tile
    const int tr = (lane & 3) * 2;     // col pair base
    const int r0a = row0 + m0 + tq;
    const int r1a = r0a + 8;
#pragma unroll
    for (int nt = 0; nt < 16; nt++) {
        const int col = nt * 8 + tr;
        const __nv_bfloat162 v01 = __floats2bfloat162_rn(acc[nt][0], acc[nt][1]);
        const __nv_bfloat162 v23 = __floats2bfloat162_rn(acc[nt][2], acc[nt][3]);
        if (r0a < N_NODES) *(__nv_bfloat162*)(out + (size_t)r0a * NHID + col) = v01;
        if (r1a < N_NODES) *(__nv_bfloat162*)(out + (size_t)r1a * NHID + col) = v23;
    }
}

// ---------------- 4) edge phase -------------------------------------------
__device__ __forceinline__ float2 edge_dots(int r, int c, int lane,
                                            float4 vb1, float4 val,
                                            float4 w20, float4 w21) {
    const uint2 pa = *(const uint2*)(g_A + (size_t)r * NHID + lane * 4);
    const uint2 pb = *(const uint2*)(g_B + (size_t)c * NHID + lane * 4);
    const float2 a01 = __bfloat1622float2(*(const __nv_bfloat162*)&pa.x);
    const float2 a23 = __bfloat1622float2(*(const __nv_bfloat162*)&pa.y);
    const float2 b01 = __bfloat1622float2(*(const __nv_bfloat162*)&pb.x);
    const float2 b23 = __bfloat1622float2(*(const __nv_bfloat162*)&pb.y);

    float h0 = a01.x + b01.x + vb1.x;
    float h1 = a01.y + b01.y + vb1.y;
    float h2 = a23.x + b23.x + vb1.z;
    float h3 = a23.y + b23.y + vb1.w;
    h0 = h0 >= 0.f ? h0 : h0 * val.x;
    h1 = h1 >= 0.f ? h1 : h1 * val.y;
    h2 = h2 >= 0.f ? h2 : h2 * val.z;
    h3 = h3 >= 0.f ? h3 : h3 * val.w;

    float2 s;
    s.x = fmaf(h0, w20.x, fmaf(h1, w20.z, fmaf(h2, w21.x, h3 * w21.z)));
    s.y = fmaf(h0, w20.y, fmaf(h1, w20.w, fmaf(h2, w21.y, h3 * w21.w)));
    return s;
}

// One warp per 2 edges per iteration (MLP across the pair).
__global__ void __launch_bounds__(256) k_edge(const float* __restrict__ b1,
                                              const float* __restrict__ alpha,
                                              const float* __restrict__ W2,
                                              const float* __restrict__ b2) {
    __shared__ float s_part[8];
    const int t = threadIdx.x;
    const int warp = t >> 5;
    const int lane = t & 31;

    const float4 vb1 = *(const float4*)(b1 + lane * 4);
    const float4 val = *(const float4*)(alpha + lane * 4);
    const float4 w20 = *(const float4*)(W2 + lane * 8);
    const float4 w21 = *(const float4*)(W2 + lane * 8 + 4);
    const float  b20 = b2[0];
    const float  b21 = b2[1];

    float wsum = 0.f;
    const int wid = blockIdx.x * 8 + warp;
    const int estep = NB_EDGE * 8 * 2;
    for (int e = wid * 2; e < N_EDGES; e += estep) {
        const int r0 = g_row[e],     c0 = g_col[e];
        const int r1 = g_row[e + 1], c1 = g_col[e + 1];
        int y0 = 0, y1 = 0;
        if (lane == 0) {
            y0 = (g_lab[r0] == g_lab[c0]) ? 1 : 0;
            y1 = (g_lab[r1] == g_lab[c1]) ? 1 : 0;
        }
        float s00, s01, s10, s11;
        {
            const float2 d0 = edge_dots(r0, c0, lane, vb1, val, w20, w21);
            const float2 d1 = edge_dots(r1, c1, lane, vb1, val, w20, w21);
            s00 = d0.x; s01 = d0.y; s10 = d1.x; s11 = d1.y;
        }
        // 4 interleaved butterfly chains (independent -> pipelined SHFLs)
#pragma unroll
        for (int o = 16; o > 0; o >>= 1) {
            s00 += __shfl_xor_sync(0xffffffffu, s00, o);
            s01 += __shfl_xor_sync(0xffffffffu, s01, o);
            s10 += __shfl_xor_sync(0xffffffffu, s10, o);
            s11 += __shfl_xor_sync(0xffffffffu, s11, o);
        }

        if (lane == 0) {
            {
                const float l0 = s00 + b20, l1 = s01 + b21;
                const float m = fmaxf(l0, l1), mn = fminf(l0, l1);
                const float lse = m + log1pf(__expf(mn - m));
                wsum += lse - (y0 ? l1 : l0);
            }
            {
                const float l0 = s10 + b20, l1 = s11 + b21;
                const float m = fmaxf(l0, l1), mn = fminf(l0, l1);
                const float lse = m + log1pf(__expf(mn - m));
                wsum += lse - (y1 ? l1 : l0);
            }
        }
    }

    if (lane == 0) s_part[warp] = wsum;
    __syncthreads();
    if (t == 0) {
        float s = 0.f;
#pragma unroll
        for (int w = 0; w < 8; w++) s += s_part[w];
        g_part[blockIdx.x] = s;
    }
}

// ---------------- 5) final reduction -> mean loss ---------------------------
__global__ void k_final(float* out, int out_size) {
    __shared__ double sm[256];
    double s = 0.0;
    for (int i = threadIdx.x; i < NB_EDGE; i += 256) s += (double)g_part[i];
    sm[threadIdx.x] = s;
    __syncthreads();
    for (int o = 128; o > 0; o >>= 1) {
        if (threadIdx.x < o) sm[threadIdx.x] += sm[threadIdx.x + o];
        __syncthreads();
    }
    if (threadIdx.x == 0) out[0] = (float)(sm[0] / (double)N_EDGES);
    for (int i = 1 + (int)threadIdx.x; i < out_size; i += 256) out[i] = 0.f;
}

// ---------------- launch ----------------------------------------------------
extern "C" void kernel_launch(void* const* d_in, const int* in_sizes, int n_in,
                              void* d_out, int out_size) {
    const float* feature = (const float*)d_in[0];
    const float* W1      = (const float*)d_in[1];
    const float* b1      = (const float*)d_in[2];
    const float* alpha   = (const float*)d_in[3];
    const float* W2      = (const float*)d_in[4];
    const float* b2      = (const float*)d_in[5];
    const void*  row     = d_in[6];
    const void*  col     = d_in[7];
    const void*  lab     = d_in[8];

    const int smem_bytes = 2 * 128 * SA_STRIDE * (int)sizeof(__nv_bfloat16);
    cudaFuncSetAttribute(k_gemm, cudaFuncAttributeMaxDynamicSharedMemorySize,
                         smem_bytes);

    k_detect<<<1, 32>>>(row);
    k_convert<<<512, 256>>>(row, col, lab);

    dim3 ggrid((N_NODES + 127) / 128, 2);
    k_gemm<<<ggrid, 256, smem_bytes>>>(feature, W1);

    k_edge<<<NB_EDGE, 256>>>(b1, alpha, W2, b2);
    k_final<<<1, 256>>>((float*)d_out, out_size);
}